// round 7
// baseline (speedup 1.0000x reference)
#include <cuda_runtime.h>
#include <math.h>
#include <float.h>

#define NN    8192
#define DIM   512
#define TOPK  10
#define SCALE 0.04419417382415922f   // 512^-0.5 rounded to fp32

typedef unsigned long long ull;

// 32 MB fp32 scratch for the two embeddings (static device alloc: allowed)
__device__ float g_e[2][NN * DIM];

// packed fp32x2 FMA (SASS FFMA2) — bit-exact IEEE fp32 per lane
#define FMA2(d, a, b) asm("fma.rn.f32x2 %0, %1, %2, %0;" : "+l"(d) : "l"(a), "l"(b))
#define PACK2(d, f)   asm("mov.b64 %0, {%1, %1};" : "=l"(d) : "f"(f))

// ---------------------------------------------------------------------------
// Kernel 1: E_z = X @ W_z^T + b_z   (z=0: Wh/bh, z=1: Wt/bt)  (unchanged)
// ---------------------------------------------------------------------------
__global__ __launch_bounds__(256) void embed_gemm(
    const float* __restrict__ X,
    const float* __restrict__ Wh, const float* __restrict__ bh,
    const float* __restrict__ Wt, const float* __restrict__ bt)
{
    const float* __restrict__ W  = blockIdx.z ? Wt : Wh;
    const float* __restrict__ bz = blockIdx.z ? bt : bh;
    float* E = g_e[blockIdx.z];

    __shared__ float As[16 * 132];
    __shared__ float Bs[16 * 68];

    const int tid = threadIdx.x;
    const int tx = tid & 15, ty = tid >> 4;
    const int brow = blockIdx.y * 128;
    const int bcol = blockIdx.x * 64;

    float acc[8][4];
    #pragma unroll
    for (int i = 0; i < 8; i++)
        #pragma unroll
        for (int j = 0; j < 4; j++) acc[i][j] = 0.f;

    for (int kt = 0; kt < DIM; kt += 16) {
        #pragma unroll
        for (int i = 0; i < 2; i++) {
            int lin = tid + i * 256;
            int r = lin >> 2, kq = (lin & 3) * 4;
            float4 v = *(const float4*)(X + (size_t)(brow + r) * DIM + kt + kq);
            As[(kq + 0) * 132 + r] = v.x; As[(kq + 1) * 132 + r] = v.y;
            As[(kq + 2) * 132 + r] = v.z; As[(kq + 3) * 132 + r] = v.w;
        }
        {
            int r = tid >> 2, kq = (tid & 3) * 4;
            float4 v = *(const float4*)(W + (size_t)(bcol + r) * DIM + kt + kq);
            Bs[(kq + 0) * 68 + r] = v.x; Bs[(kq + 1) * 68 + r] = v.y;
            Bs[(kq + 2) * 68 + r] = v.z; Bs[(kq + 3) * 68 + r] = v.w;
        }
        __syncthreads();
        #pragma unroll
        for (int kk = 0; kk < 16; kk++) {
            float4 a0 = *(float4*)(As + kk * 132 + 4 * ty);
            float4 a1 = *(float4*)(As + kk * 132 + 64 + 4 * ty);
            float4 b  = *(float4*)(Bs + kk * 68 + 4 * tx);
            float av[8] = {a0.x, a0.y, a0.z, a0.w, a1.x, a1.y, a1.z, a1.w};
            float bw[4] = {b.x, b.y, b.z, b.w};
            #pragma unroll
            for (int i = 0; i < 8; i++)
                #pragma unroll
                for (int j = 0; j < 4; j++)
                    acc[i][j] = fmaf(av[i], bw[j], acc[i][j]);
        }
        __syncthreads();
    }
    float4 bb = *(const float4*)(bz + bcol + 4 * tx);
    #pragma unroll
    for (int i = 0; i < 8; i++) {
        int row = brow + ((i < 4) ? (4 * ty + i) : (64 + 4 * ty + (i - 4)));
        float4 o;
        o.x = acc[i][0] + bb.x; o.y = acc[i][1] + bb.y;
        o.z = acc[i][2] + bb.z; o.w = acc[i][3] + bb.w;
        *(float4*)(E + (size_t)row * DIM + bcol + 4 * tx) = o;
    }
}

// ---------------------------------------------------------------------------
// Kernel 2: fused logits GEMM (packed f32x2) + per-row top-10 + softmax.
// 512 threads (16 warps, 4/SMSP). CTA = 64 rows x 8192 cols, 256-col tiles.
// Thread tile 8x4: warp w: rows 8*(w&7).. ; col half (w>>3)*128 + 4*lane.
// ---------------------------------------------------------------------------
#define LDA   68
#define LDB2  260
#define LDL2  268
#define AH_FLOATS (DIM * LDA)           // 34816
#define LS_FLOATS (64 * LDL2)           // 17152
#define BUF_STRIDE (16 * LDB2)          // 4160  (2 bufs alias low part of Ls)
#define SMEM_FLOATS (AH_FLOATS + LS_FLOATS)   // 51968 -> 207872 B

__global__ __launch_bounds__(512) void logits_topk(float* __restrict__ out)
{
    extern __shared__ float sm[];
    float* Ah  = sm;                    // [k][row]  e_h tile, transposed
    float* Ls  = sm + AH_FLOATS;        // [64][268] logits tile / merge scratch
    float* Bsm = Ls;                    // [2][16][260]  aliases Ls (disjoint lifetime)

    const float* __restrict__ eh = g_e[0];
    const float* __restrict__ et = g_e[1];

    const int tid  = threadIdx.x;
    const int lane = tid & 31;
    const int w    = tid >> 5;          // 0..15
    const int rg   = w & 7;             // row group: rows 8*rg..8*rg+7
    const int ch   = w >> 3;            // col half: cols ch*128 + 4*lane

    const int brow = blockIdx.x * 64;

    // ---- phase 0: load e_h rows [64][512] -> Ah[k][row] ----
    #pragma unroll
    for (int i = 0; i < 16; i++) {
        int lin = tid + i * 512;
        int r = lin >> 7;
        int kq = (lin & 127) * 4;
        float4 v = *(const float4*)(eh + (size_t)(brow + r) * DIM + kq);
        Ah[(kq + 0) * LDA + r] = v.x; Ah[(kq + 1) * LDA + r] = v.y;
        Ah[(kq + 2) * LDA + r] = v.z; Ah[(kq + 3) * LDA + r] = v.w;
    }

    // per-thread partial top-10: row = tid>>3, interleaved 4-col chunks
    float tv[TOPK]; int ti[TOPK];
    #pragma unroll
    for (int s = 0; s < TOPK; s++) { tv[s] = -FLT_MAX; ti[s] = 0; }
    const int qr = tid >> 3;            // 0..63
    const int qq = tid & 7;             // chunk phase 0..7

    // B loader: 256 et-rows x 16 k per chunk; 2 float4 per thread
    const int lr = tid >> 2;            // 0..127 (second load: +128)
    const int lk = (tid & 3) * 4;

    __syncthreads();

    for (int ct = 0; ct < NN; ct += 256) {
        // prime k-chunk 0 into buf 0
        float4 p0 = *(const float4*)(et + (size_t)(ct + lr) * DIM + lk);
        float4 p1 = *(const float4*)(et + (size_t)(ct + lr + 128) * DIM + lk);
        Bsm[(lk + 0) * LDB2 + lr] = p0.x; Bsm[(lk + 1) * LDB2 + lr] = p0.y;
        Bsm[(lk + 2) * LDB2 + lr] = p0.z; Bsm[(lk + 3) * LDB2 + lr] = p0.w;
        Bsm[(lk + 0) * LDB2 + lr + 128] = p1.x; Bsm[(lk + 1) * LDB2 + lr + 128] = p1.y;
        Bsm[(lk + 2) * LDB2 + lr + 128] = p1.z; Bsm[(lk + 3) * LDB2 + lr + 128] = p1.w;
        __syncthreads();

        ull acc[8][2];
        #pragma unroll
        for (int i = 0; i < 8; i++) { acc[i][0] = 0ull; acc[i][1] = 0ull; }

        #pragma unroll 1
        for (int kt = 0; kt < 32; kt++) {
            const float* Bc = Bsm + (kt & 1) * BUF_STRIDE;
            float* Bn = Bsm + ((kt & 1) ^ 1) * BUF_STRIDE;
            if (kt < 31) {
                p0 = *(const float4*)(et + (size_t)(ct + lr) * DIM + (kt + 1) * 16 + lk);
                p1 = *(const float4*)(et + (size_t)(ct + lr + 128) * DIM + (kt + 1) * 16 + lk);
            }
            #pragma unroll
            for (int kk = 0; kk < 16; kk++) {
                float4 a0 = *(const float4*)(Ah + (kt * 16 + kk) * LDA + 8 * rg);
                float4 a1 = *(const float4*)(Ah + (kt * 16 + kk) * LDA + 8 * rg + 4);
                ulonglong2 b = *(const ulonglong2*)(Bc + kk * LDB2 + ch * 128 + 4 * lane);
                ull ap[8];
                PACK2(ap[0], a0.x); PACK2(ap[1], a0.y);
                PACK2(ap[2], a0.z); PACK2(ap[3], a0.w);
                PACK2(ap[4], a1.x); PACK2(ap[5], a1.y);
                PACK2(ap[6], a1.z); PACK2(ap[7], a1.w);
                #pragma unroll
                for (int i = 0; i < 8; i++) {
                    FMA2(acc[i][0], ap[i], b.x);
                    FMA2(acc[i][1], ap[i], b.y);
                }
            }
            if (kt < 31) {
                Bn[(lk + 0) * LDB2 + lr] = p0.x; Bn[(lk + 1) * LDB2 + lr] = p0.y;
                Bn[(lk + 2) * LDB2 + lr] = p0.z; Bn[(lk + 3) * LDB2 + lr] = p0.w;
                Bn[(lk + 0) * LDB2 + lr + 128] = p1.x; Bn[(lk + 1) * LDB2 + lr + 128] = p1.y;
                Bn[(lk + 2) * LDB2 + lr + 128] = p1.z; Bn[(lk + 3) * LDB2 + lr + 128] = p1.w;
            }
            __syncthreads();
        }

        // dump tile to smem (packed pairs stored verbatim = exact fp32 values)
        #pragma unroll
        for (int i = 0; i < 8; i++) {
            ulonglong2 o; o.x = acc[i][0]; o.y = acc[i][1];
            *(ulonglong2*)(Ls + (8 * rg + i) * LDL2 + ch * 128 + 4 * lane) = o;
        }
        __syncthreads();

        // scan: 8 threads/row, each reads 8 interleaved float4 chunks (asc cols)
        {
            const float* Lr = Ls + qr * LDL2 + qq * 4;
            #pragma unroll
            for (int b8 = 0; b8 < 8; b8++) {
                float4 v4 = *(const float4*)(Lr + 32 * b8);
                int cbase = ct + qq * 4 + 32 * b8;
                float vv[4] = {v4.x, v4.y, v4.z, v4.w};
                #pragma unroll
                for (int e = 0; e < 4; e++) {
                    float v = vv[e];
                    if (v > tv[TOPK - 1]) {
                        float cv = v; int ci = cbase + e;
                        #pragma unroll
                        for (int s = 0; s < TOPK; s++) {
                            if (cv > tv[s]) {
                                float tf = tv[s]; tv[s] = cv; cv = tf;
                                int tii = ti[s];  ti[s] = ci; ci = tii;
                            }
                        }
                    }
                }
            }
        }
        __syncthreads();
    }

    // ---- merge 8 partial lists per row, softmax, emit ----
    float* candv = Ls;                       // [64][80]
    int*   candi = (int*)(Ls + 64 * 80);     // [64][80]
    #pragma unroll
    for (int s = 0; s < TOPK; s++) {
        candv[qr * 80 + qq * TOPK + s] = tv[s];
        candi[qr * 80 + qq * TOPK + s] = ti[s];
    }
    __syncthreads();

    if (tid < 64) {
        int r = tid;
        float wv[TOPK]; int wi[TOPK];
        #pragma unroll
        for (int s = 0; s < TOPK; s++) {
            float bvv = -FLT_MAX; int bii = 0x7fffffff; int bc = 0;
            for (int c = 0; c < 80; c++) {
                float v = candv[r * 80 + c];
                int  ii = candi[r * 80 + c];
                if (v > bvv || (v == bvv && ii < bii)) { bvv = v; bii = ii; bc = c; }
            }
            candv[r * 80 + bc] = -FLT_MAX;
            wv[s] = bvv; wi[s] = bii;
        }
        float pw[TOPK], psum = 0.f;
        #pragma unroll
        for (int s = 0; s < TOPK; s++) {
            pw[s] = __expf((wv[s] - wv[0]) * SCALE);
            psum += pw[s];
        }
        float inv = 1.0f / psum;
        int row = brow + r;
        #pragma unroll
        for (int s = 0; s < TOPK; s++) {
            out[(size_t)row * TOPK + s]                         = (float)row;
            out[(size_t)NN * TOPK + (size_t)row * TOPK + s]     = (float)wi[s];
            out[(size_t)2 * NN * TOPK + (size_t)row * TOPK + s] = pw[s] * inv;
        }
    }
}

// ---------------------------------------------------------------------------
extern "C" void kernel_launch(void* const* d_in, const int* in_sizes, int n_in,
                              void* d_out, int out_size)
{
    const float* X  = (const float*)d_in[0];
    const float* Wh = (const float*)d_in[1];
    const float* bh = (const float*)d_in[2];
    const float* Wt = (const float*)d_in[3];
    const float* bt = (const float*)d_in[4];
    float* out = (float*)d_out;

    cudaFuncSetAttribute(logits_topk, cudaFuncAttributeMaxDynamicSharedMemorySize,
                         SMEM_FLOATS * sizeof(float));

    embed_gemm<<<dim3(DIM / 64, NN / 128, 2), 256>>>(X, Wh, bh, Wt, bt);
    logits_topk<<<NN / 64, 512, SMEM_FLOATS * sizeof(float)>>>(out);
}